// round 1
// baseline (speedup 1.0000x reference)
#include <cuda_runtime.h>
#include <cuda_bf16.h>
#include <math.h>

#define BB   2
#define CC   64
#define NPTS 20000
#define KK   16
#define CO   64
#define NODES (BB * NPTS)

// Scratch (device globals: allocation-free rule)
__device__ float g_U[NODES * CO];     // (W1-W2) @ x   per node
__device__ float g_V[NODES * CO];     // W2      @ x   per node
__device__ float g_posT[NODES * 4];   // pos transposed to [node][4]

// ---------------------------------------------------------------------------
// Kernel 1: per-node transform u = (W1-W2) x, v = W2 x ; also transpose pos.
// One thread per node. Weights staged in shared, transposed to [c][o] so the
// inner loop does float4 broadcast loads (4x LDS.128 : 16 FMA).
// ---------------------------------------------------------------------------
__global__ __launch_bounds__(256) void uv_kernel(const float* __restrict__ x,
                                                 const float* __restrict__ pos,
                                                 const float* __restrict__ W) {
    __shared__ float AsT[64 * 64];   // (W1-W2)^T : [c][o]
    __shared__ float W2T[64 * 64];   // W2^T      : [c][o]

    int tid = threadIdx.x;
    for (int i = tid; i < 64 * 64; i += blockDim.x) {
        int o = i >> 6, c = i & 63;
        float w1 = W[o * 128 + c];
        float w2 = W[o * 128 + 64 + c];
        AsT[c * 64 + o] = w1 - w2;
        W2T[c * 64 + o] = w2;
    }
    __syncthreads();

    int node = blockIdx.x * blockDim.x + tid;
    if (node >= NODES) return;
    int b = node / NPTS;
    int n = node - b * NPTS;

    // pos transpose: [B,3,N] -> [node][4]
    {
        const float* pb = pos + b * 3 * NPTS + n;
        float4 p;
        p.x = pb[0 * NPTS];
        p.y = pb[1 * NPTS];
        p.z = pb[2 * NPTS];
        p.w = 0.0f;
        reinterpret_cast<float4*>(g_posT)[node] = p;
    }

    // Load this node's feature column (coalesced across threads: n varies)
    const float* xb = x + b * CC * NPTS + n;
    float xr[64];
#pragma unroll
    for (int c = 0; c < 64; ++c) xr[c] = xb[c * NPTS];

    float* Uo = g_U + node * 64;
    float* Vo = g_V + node * 64;

    for (int o0 = 0; o0 < 64; o0 += 8) {
        float au[8], av[8];
#pragma unroll
        for (int j = 0; j < 8; ++j) { au[j] = 0.0f; av[j] = 0.0f; }

#pragma unroll
        for (int c = 0; c < 64; ++c) {
            float xv = xr[c];
            const float4* a4 = reinterpret_cast<const float4*>(AsT + c * 64 + o0);
            const float4* w4 = reinterpret_cast<const float4*>(W2T + c * 64 + o0);
            float4 a0 = a4[0], a1 = a4[1];
            float4 w0 = w4[0], w1 = w4[1];
            au[0] = fmaf(a0.x, xv, au[0]);
            au[1] = fmaf(a0.y, xv, au[1]);
            au[2] = fmaf(a0.z, xv, au[2]);
            au[3] = fmaf(a0.w, xv, au[3]);
            au[4] = fmaf(a1.x, xv, au[4]);
            au[5] = fmaf(a1.y, xv, au[5]);
            au[6] = fmaf(a1.z, xv, au[6]);
            au[7] = fmaf(a1.w, xv, au[7]);
            av[0] = fmaf(w0.x, xv, av[0]);
            av[1] = fmaf(w0.y, xv, av[1]);
            av[2] = fmaf(w0.z, xv, av[2]);
            av[3] = fmaf(w0.w, xv, av[3]);
            av[4] = fmaf(w1.x, xv, av[4]);
            av[5] = fmaf(w1.y, xv, av[5]);
            av[6] = fmaf(w1.z, xv, av[6]);
            av[7] = fmaf(w1.w, xv, av[7]);
        }
        float4* U4 = reinterpret_cast<float4*>(Uo + o0);
        float4* V4 = reinterpret_cast<float4*>(Vo + o0);
        U4[0] = make_float4(au[0], au[1], au[2], au[3]);
        U4[1] = make_float4(au[4], au[5], au[6], au[7]);
        V4[0] = make_float4(av[0], av[1], av[2], av[3]);
        V4[1] = make_float4(av[4], av[5], av[6], av[7]);
    }
}

// ---------------------------------------------------------------------------
// Kernel 2: per-edge combine + suppression + max over K.
// One warp per point (32 warps / block = 32 consecutive points).
// Lane l owns outputs 2l and 2l+1 (float2). Results staged in shared for
// coalesced [CO, N] stores.
// ---------------------------------------------------------------------------
__global__ __launch_bounds__(1024) void edge_kernel(const int* __restrict__ ei,
                                                    const float* __restrict__ bias,
                                                    float* __restrict__ out) {
    __shared__ float sm[32 * 66];  // [nn][o] padded to 66 to dodge bank conflicts

    int tid  = threadIdx.x;
    int warp = tid >> 5;
    int lane = tid & 31;

    int g = blockIdx.x * 32 + warp;   // global point index (block never crosses batch: 20000 % 32 == 0)
    int b = g / NPTS;
    int n = g - b * NPTS;

    const int* e0 = ei + (b * NPTS + n) * KK;                    // edge_index[0] (neighbor)
    const int* e1 = ei + (BB * NPTS * KK) + (b * NPTS + n) * KK; // edge_index[1] (center)

    float2 bb = reinterpret_cast<const float2*>(bias)[lane];

    const float*  Ub = g_U + b * NPTS * 64;
    const float*  Vb = g_V + b * NPTS * 64;
    const float4* Pb = reinterpret_cast<const float4*>(g_posT) + b * NPTS;

    float m0 = 0.0f, m1 = 0.0f;  // relu*positive-suppression => outputs >= 0

#pragma unroll 4
    for (int k = 0; k < KK; ++k) {
        int i1 = e1[k];
        int i0 = e0[k];
        float2 u = reinterpret_cast<const float2*>(Ub + i1 * 64)[lane];
        float2 v = reinterpret_cast<const float2*>(Vb + i0 * 64)[lane];
        float4 p1 = Pb[i1];
        float4 p0 = Pb[i0];
        float dx = p1.x - p0.x, dy = p1.y - p0.y, dz = p1.z - p0.z;
        float dis = sqrtf(dx * dx + dy * dy + dz * dz);
        float s = 2.0f / (1.0f + __expf(dis));   // 2*sigmoid(-dis)
        float y0 = fmaxf(u.x + v.x + bb.x, 0.0f) * s;
        float y1 = fmaxf(u.y + v.y + bb.y, 0.0f) * s;
        m0 = fmaxf(m0, y0);
        m1 = fmaxf(m1, y1);
    }

    // stage: sm[nn(=warp)][o]; lane writes float2 at o = 2*lane (conflict-free)
    reinterpret_cast<float2*>(sm + warp * 66)[lane] = make_float2(m0, m1);
    __syncthreads();

    int b2 = (blockIdx.x * 32) / NPTS;
    int n0 = (blockIdx.x * 32) - b2 * NPTS;
    // 64 outputs x 32 points = 2048 values, 1024 threads -> 2 each, coalesced over nn
    for (int e = tid; e < CO * 32; e += 1024) {
        int o  = e >> 5;
        int nn = e & 31;
        out[(b2 * CO + o) * NPTS + n0 + nn] = sm[nn * 66 + o];
    }
}

extern "C" void kernel_launch(void* const* d_in, const int* in_sizes, int n_in,
                              void* d_out, int out_size) {
    const float* x    = (const float*)d_in[0];
    const int*   ei   = (const int*)d_in[1];
    const float* pos  = (const float*)d_in[2];
    const float* W    = (const float*)d_in[3];
    const float* bias = (const float*)d_in[4];
    float* out = (float*)d_out;

    uv_kernel<<<(NODES + 255) / 256, 256>>>(x, pos, W);
    edge_kernel<<<NODES / 32, 1024>>>(ei, bias, out);
}

// round 2
// speedup vs baseline: 1.4636x; 1.4636x over previous
#include <cuda_runtime.h>
#include <cuda_bf16.h>
#include <math.h>

#define BB   2
#define CC   64
#define NPTS 20000
#define KK   16
#define CO   64
#define NODES (BB * NPTS)

// Scratch (device globals: allocation-free rule)
__device__ float g_U[NODES * CO];     // (W1-W2) @ x   per node
__device__ float g_V[NODES * CO];     // W2      @ x   per node
__device__ float g_posT[NODES * 4];   // pos transposed to [node][4]

// Packed fp32x2 FMA (Blackwell): d = a*b + d, two fp32 lanes per instruction.
#define FMA2(d, a, b) \
    asm("fma.rn.f32x2 %0, %1, %2, %0;" : "+l"(d) : "l"(a), "l"(b))

__device__ __forceinline__ unsigned long long pack2(float lo, float hi) {
    unsigned long long r;
    asm("mov.b64 %0, {%1, %2};" : "=l"(r) : "r"(__float_as_uint(lo)), "r"(__float_as_uint(hi)));
    return r;
}

// ---------------------------------------------------------------------------
// Kernel 1: per-node transform. sW[c][o] combined: o<64 -> (W1-W2)^T,
// o>=64 -> W2^T. One thread per node, 128 outputs in 4 chunks of 32, packed
// f32x2 accumulators (FFMA2 halves FMA issue count). Also transposes pos.
// ---------------------------------------------------------------------------
__global__ __launch_bounds__(256) void uv_kernel(const float* __restrict__ x,
                                                 const float* __restrict__ pos,
                                                 const float* __restrict__ W) {
    __shared__ float sW[64 * 128];   // [c][o], 32 KB

    int tid = threadIdx.x;
    for (int i = tid; i < 64 * 128; i += 256) {
        int c = i >> 7, o = i & 127;
        float w;
        if (o < 64)
            w = W[o * 128 + c] - W[o * 128 + 64 + c];   // W1 - W2
        else
            w = W[(o - 64) * 128 + 64 + c];             // W2
        sW[c * 128 + o] = w;
    }
    __syncthreads();

    int node = blockIdx.x * 256 + tid;
    if (node >= NODES) return;
    int b = node / NPTS;
    int n = node - b * NPTS;

    // pos transpose: [B,3,N] -> [node][4]
    {
        const float* pb = pos + b * 3 * NPTS + n;
        float4 p;
        p.x = pb[0];
        p.y = pb[NPTS];
        p.z = pb[2 * NPTS];
        p.w = 0.0f;
        reinterpret_cast<float4*>(g_posT)[node] = p;
    }

    // Load this node's feature column (coalesced: n varies across threads)
    const float* xb = x + b * CC * NPTS + n;
    float xr[64];
#pragma unroll
    for (int c = 0; c < 64; ++c) xr[c] = xb[c * NPTS];

#pragma unroll 1
    for (int q = 0; q < 4; ++q) {
        unsigned long long acc[16];
#pragma unroll
        for (int t = 0; t < 16; ++t) acc[t] = 0ull;   // bit pattern of (0.f, 0.f)

#pragma unroll
        for (int c = 0; c < 64; ++c) {
            unsigned long long xp = pack2(xr[c], xr[c]);
            const ulonglong2* wp =
                reinterpret_cast<const ulonglong2*>(sW + c * 128 + q * 32);
#pragma unroll
            for (int t = 0; t < 8; ++t) {
                ulonglong2 w = wp[t];           // 4 weights (2 packed operands)
                FMA2(acc[2 * t],     w.x, xp);
                FMA2(acc[2 * t + 1], w.y, xp);
            }
        }

        // chunks 0,1 -> U[0:64); chunks 2,3 -> V[0:64)
        float* dstf = (q < 2) ? (g_U + node * 64 + q * 32)
                              : (g_V + node * 64 + (q - 2) * 32);
        ulonglong2* dst = reinterpret_cast<ulonglong2*>(dstf);
#pragma unroll
        for (int t = 0; t < 8; ++t)
            dst[t] = make_ulonglong2(acc[2 * t], acc[2 * t + 1]);
    }
}

// ---------------------------------------------------------------------------
// Kernel 2: per-edge combine + suppression + max over K.
// One warp per point, 8 warps/block. Lanes 0..15 precompute indices and the
// suppression factor for their k (distributed via shfl). Gathers prefetched
// in chunks of 4 (8 loads in flight per warp). Shared staging for coalesced
// [CO, N] stores.
// ---------------------------------------------------------------------------
__global__ __launch_bounds__(256) void edge_kernel(const int* __restrict__ ei,
                                                   const float* __restrict__ bias,
                                                   float* __restrict__ out) {
    __shared__ float sm[8 * 66];

    int tid  = threadIdx.x;
    int warp = tid >> 5;
    int lane = tid & 31;

    int g = blockIdx.x * 8 + warp;   // 20000 % 8 == 0 -> block never crosses batch
    int b = g / NPTS;
    int n = g - b * NPTS;

    const int* e0 = ei + (b * NPTS + n) * KK;                    // neighbor idx
    const int* e1 = ei + (BB * NPTS * KK) + (b * NPTS + n) * KK; // center idx

    const float*  Ub = g_U + b * NPTS * 64;
    const float*  Vb = g_V + b * NPTS * 64;
    const float4* Pb = reinterpret_cast<const float4*>(g_posT) + b * NPTS;

    // lanes 0..15: own one k each -> indices + suppression factor
    int   i0l = 0, i1l = 0;
    float sl  = 0.0f;
    if (lane < KK) {
        i0l = e0[lane];
        i1l = e1[lane];
        float4 p1 = Pb[i1l];
        float4 p0 = Pb[i0l];
        float dx = p1.x - p0.x, dy = p1.y - p0.y, dz = p1.z - p0.z;
        float dis = sqrtf(dx * dx + dy * dy + dz * dz);
        sl = 2.0f / (1.0f + __expf(dis));   // 2*sigmoid(-dis)
    }

    float2 bb = reinterpret_cast<const float2*>(bias)[lane];

    float m0 = 0.0f, m1 = 0.0f;  // relu * positive factor => result >= 0

#pragma unroll
    for (int k0 = 0; k0 < KK; k0 += 4) {
        float2 u[4], v[4];
        float  s[4];
#pragma unroll
        for (int j = 0; j < 4; ++j) {
            int i1 = __shfl_sync(0xFFFFFFFFu, i1l, k0 + j);
            int i0 = __shfl_sync(0xFFFFFFFFu, i0l, k0 + j);
            s[j]   = __shfl_sync(0xFFFFFFFFu, sl,  k0 + j);
            u[j] = reinterpret_cast<const float2*>(Ub + i1 * 64)[lane];
            v[j] = reinterpret_cast<const float2*>(Vb + i0 * 64)[lane];
        }
#pragma unroll
        for (int j = 0; j < 4; ++j) {
            float y0 = fmaxf(u[j].x + v[j].x + bb.x, 0.0f) * s[j];
            float y1 = fmaxf(u[j].y + v[j].y + bb.y, 0.0f) * s[j];
            m0 = fmaxf(m0, y0);
            m1 = fmaxf(m1, y1);
        }
    }

    reinterpret_cast<float2*>(sm + warp * 66)[lane] = make_float2(m0, m1);
    __syncthreads();

    int base = blockIdx.x * 8;
    int b2 = base / NPTS;
    int n0 = base - b2 * NPTS;
    // 64 outputs x 8 points = 512 values, 256 threads -> 2 each
#pragma unroll
    for (int e = tid; e < CO * 8; e += 256) {
        int o  = e >> 3;
        int nn = e & 7;
        out[(b2 * CO + o) * NPTS + n0 + nn] = sm[nn * 66 + o];
    }
}

extern "C" void kernel_launch(void* const* d_in, const int* in_sizes, int n_in,
                              void* d_out, int out_size) {
    const float* x    = (const float*)d_in[0];
    const int*   ei   = (const int*)d_in[1];
    const float* pos  = (const float*)d_in[2];
    const float* W    = (const float*)d_in[3];
    const float* bias = (const float*)d_in[4];
    float* out = (float*)d_out;

    uv_kernel<<<(NODES + 255) / 256, 256>>>(x, pos, W);
    edge_kernel<<<NODES / 8, 256>>>(ei, bias, out);
}